// round 16
// baseline (speedup 1.0000x reference)
#include <cuda_runtime.h>
#include <cuda_bf16.h>
#include <math.h>
#include <cstdint>

// ---------------- problem constants ----------------
#define B_    8
#define S_    256
#define SKV_  1024
#define H_    512
#define NH_   8
#define HD_   64
#define G4_   2048
#define V_    32000
#define BT_   (B_*S_)         // 2048
#define BKV_  (B_*SKV_)       // 8192
#define K_GEMM 512

// ---------------- device scratch ----------------
__device__ float    g_xg  [BT_  * (size_t)G4_];
__device__ float    g_V   [BKV_ * (size_t)H_];
__device__ float    g_H   [BT_  * (size_t)H_];
__device__ float    g_hcur[B_ * H_];
__device__ float    g_att [(size_t)B_ * NH_ * S_ * SKV_];
__device__ unsigned g_flags[128];
// split-bf16 operand buffers
__device__ __nv_bfloat16 g_embhi[(size_t)V_ * H_];
__device__ __nv_bfloat16 g_emblo[(size_t)V_ * H_];
__device__ __nv_bfloat16 g_outhi[(size_t)BT_ * H_];
__device__ __nv_bfloat16 g_outlo[(size_t)BT_ * H_];
__device__ __nv_bfloat16 g_enchi[(size_t)BKV_ * H_];
__device__ __nv_bfloat16 g_enclo[(size_t)BKV_ * H_];
__device__ __nv_bfloat16 g_wihhi[(size_t)G4_ * H_];
__device__ __nv_bfloat16 g_wihlo[(size_t)G4_ * H_];
__device__ __nv_bfloat16 g_wqhi[(size_t)H_ * H_];
__device__ __nv_bfloat16 g_wqlo[(size_t)H_ * H_];
__device__ __nv_bfloat16 g_wkhi[(size_t)H_ * H_];
__device__ __nv_bfloat16 g_wklo[(size_t)H_ * H_];
__device__ __nv_bfloat16 g_wvhi[(size_t)H_ * H_];
__device__ __nv_bfloat16 g_wvlo[(size_t)H_ * H_];
__device__ __nv_bfloat16 g_wohi[(size_t)H_ * H_];
__device__ __nv_bfloat16 g_wolo[(size_t)H_ * H_];
__device__ __nv_bfloat16 g_Hhi [(size_t)BT_ * H_];
__device__ __nv_bfloat16 g_Hlo [(size_t)BT_ * H_];
__device__ __nv_bfloat16 g_ctxhi[(size_t)BT_ * H_];
__device__ __nv_bfloat16 g_ctxlo[(size_t)BT_ * H_];
// attention operands
__device__ __nv_bfloat16 g_Qhi [(size_t)BT_ * H_];
__device__ __nv_bfloat16 g_Qlo [(size_t)BT_ * H_];
__device__ __nv_bfloat16 g_Khi [(size_t)BKV_ * H_];
__device__ __nv_bfloat16 g_Klo [(size_t)BKV_ * H_];
__device__ __nv_bfloat16 g_atth[(size_t)B_ * NH_ * S_ * SKV_];
__device__ __nv_bfloat16 g_attl[(size_t)B_ * NH_ * S_ * SKV_];
__device__ __nv_bfloat16 g_VThi[(size_t)B_ * H_ * SKV_];
__device__ __nv_bfloat16 g_VTlo[(size_t)B_ * H_ * SKV_];

// ---------------- helpers ----------------
#define CP_ASYNC16(dst, src) \
    asm volatile("cp.async.cg.shared.global [%0], [%1], 16;" :: "r"(dst), "l"(src))
#define CP_COMMIT() asm volatile("cp.async.commit_group;" ::: "memory")
#define CP_WAIT0()  asm volatile("cp.async.wait_group 0;" ::: "memory")
#define CP_WAIT1()  asm volatile("cp.async.wait_group 1;" ::: "memory")
#define CP_WAIT2()  asm volatile("cp.async.wait_group 2;" ::: "memory")

__device__ __forceinline__ uint32_t smem_u32(const void* p) {
    uint32_t a;
    asm("{ .reg .u64 t; cvta.to.shared.u64 t, %1; cvt.u32.u64 %0, t; }"
        : "=r"(a) : "l"(p));
    return a;
}
#define LDMATRIX_X4(r0, r1, r2, r3, addr) \
    asm volatile("ldmatrix.sync.aligned.m8n8.x4.shared.b16 {%0,%1,%2,%3}, [%4];" \
        : "=r"(r0), "=r"(r1), "=r"(r2), "=r"(r3) : "r"(addr))
#define MMA16816(acc, a, b0v, b1v) \
    asm volatile( \
        "mma.sync.aligned.m16n8k16.row.col.f32.bf16.bf16.f32 " \
        "{%0,%1,%2,%3}, {%4,%5,%6,%7}, {%8,%9}, {%0,%1,%2,%3};\n" \
        : "+f"((acc)[0]), "+f"((acc)[1]), "+f"((acc)[2]), "+f"((acc)[3]) \
        : "r"((a)[0]), "r"((a)[1]), "r"((a)[2]), "r"((a)[3]), "r"(b0v), "r"(b1v))

__device__ __forceinline__ void split2(float v, __nv_bfloat16& h, __nv_bfloat16& l) {
    h = __float2bfloat16(v);
    l = __float2bfloat16(v - __bfloat162float(h));
}

// ===========================================================================
// fp32 -> (bf16 hi, bf16 lo) split
// ===========================================================================
__global__ void __launch_bounds__(256) split_bf16_k(
    const float* __restrict__ x, __nv_bfloat16* __restrict__ hi,
    __nv_bfloat16* __restrict__ lo, int n4)
{
    int base = blockIdx.x * 1024 + threadIdx.x;
    float4 v[4];
    bool p[4];
#pragma unroll
    for (int j = 0; j < 4; j++) {
        int idx = base + j * 256;
        p[j] = idx < n4;
        if (p[j]) v[j] = ((const float4*)x)[idx];
    }
#pragma unroll
    for (int j = 0; j < 4; j++) {
        if (!p[j]) continue;
        int idx = base + j * 256;
        __nv_bfloat16 h0,h1,h2,h3,l0,l1,l2,l3;
        split2(v[j].x,h0,l0); split2(v[j].y,h1,l1);
        split2(v[j].z,h2,l2); split2(v[j].w,h3,l3);
        __nv_bfloat162* hp = (__nv_bfloat162*)(hi + (size_t)idx * 4);
        __nv_bfloat162* lp = (__nv_bfloat162*)(lo + (size_t)idx * 4);
        hp[0] = __nv_bfloat162(h0,h1); hp[1] = __nv_bfloat162(h2,h3);
        lp[0] = __nv_bfloat162(l0,l1); lp[1] = __nv_bfloat162(l2,l3);
    }
}

// ===========================================================================
// Dense split-bf16 TN GEMM with optional epilogue-fused bf16 hi/lo output
// ===========================================================================
#define LGS_STAGE  20480
#define LGS_BOFF   10240
#define LGS_SMEM   (4 * LGS_STAGE)

__global__ void __launch_bounds__(256, 2) hgemm_tn_mma(
    int ldc,
    const __nv_bfloat16* __restrict__ Ahi, const __nv_bfloat16* __restrict__ Alo,
    const int* __restrict__ gidx,
    const __nv_bfloat16* __restrict__ Bhi, const __nv_bfloat16* __restrict__ Blo,
    const float* __restrict__ bias1, const float* __restrict__ bias2,
    float* __restrict__ C,
    __nv_bfloat16* __restrict__ Chi, __nv_bfloat16* __restrict__ Clo)
{
    extern __shared__ char smem[];
    const uint32_t sbase = smem_u32(smem);
    const int tid  = threadIdx.x;
    const int lane = tid & 31;
    const int warp = tid >> 5;
    const int wm   = warp >> 1, wn = warp & 1;
    const int g    = lane >> 2, t4 = lane & 3;
    const int m0   = blockIdx.x * 128;
    const int n0   = blockIdx.y * 128;

    float acc[2][8][4];
#pragma unroll
    for (int mi = 0; mi < 2; mi++)
#pragma unroll
        for (int ni = 0; ni < 8; ni++)
#pragma unroll
            for (int f = 0; f < 4; f++) acc[mi][ni][f] = 0.f;

    const int c0r = (tid)       >> 2, c0k = ((tid)       & 3) * 8;
    const int c1r = (tid + 256) >> 2, c1k = ((tid + 256) & 3) * 8;
    int ar0 = m0 + c0r, ar1 = m0 + c1r;
    if (gidx) { ar0 = gidx[ar0]; ar1 = gidx[ar1]; }
    const int br0 = n0 + c0r, br1 = n0 + c1r;

    const int lm_row = lane & 15;
    const int lm_col = (lane >> 4) * 16;

    auto issue = [&](int t, int buf) {
        const int seg  = t >> 4;
        const int kofs = (t & 15) * 32;
        const __nv_bfloat16* Ap = (seg < 2)  ? Ahi : Alo;
        const __nv_bfloat16* Bp = (seg == 1) ? Blo : Bhi;
        const uint32_t sA = sbase + buf * LGS_STAGE;
        const uint32_t sB = sA + LGS_BOFF;
        CP_ASYNC16(sA + c0r * 80 + c0k * 2, Ap + (size_t)ar0 * K_GEMM + kofs + c0k);
        CP_ASYNC16(sA + c1r * 80 + c1k * 2, Ap + (size_t)ar1 * K_GEMM + kofs + c1k);
        CP_ASYNC16(sB + c0r * 80 + c0k * 2, Bp + (size_t)br0 * K_GEMM + kofs + c0k);
        CP_ASYNC16(sB + c1r * 80 + c1k * 2, Bp + (size_t)br1 * K_GEMM + kofs + c1k);
    };

    issue(0, 0); CP_COMMIT();
    issue(1, 1); CP_COMMIT();
    issue(2, 2); CP_COMMIT();

    for (int t = 0; t < 48; t++) {
        if (t < 46)       { CP_WAIT2(); }
        else if (t == 46) { CP_WAIT1(); }
        else              { CP_WAIT0(); }
        __syncthreads();
        if (t + 3 < 48) { issue(t + 3, (t + 3) & 3); CP_COMMIT(); }

        const uint32_t sA = sbase + (t & 3) * LGS_STAGE;
        const uint32_t sB = sA + LGS_BOFF;

#pragma unroll
        for (int k0 = 0; k0 < 2; k0++) {
            const uint32_t kb = k0 * 32 + lm_col;
            uint32_t a[2][4];
#pragma unroll
            for (int mi = 0; mi < 2; mi++) {
                uint32_t addr = sA + (uint32_t)(wm * 32 + mi * 16 + lm_row) * 80 + kb;
                LDMATRIX_X4(a[mi][0], a[mi][1], a[mi][2], a[mi][3], addr);
            }
            uint32_t bf[4][4];
#pragma unroll
            for (int nj = 0; nj < 4; nj++) {
                uint32_t addr = sB + (uint32_t)(wn * 64 + nj * 16 + lm_row) * 80 + kb;
                LDMATRIX_X4(bf[nj][0], bf[nj][1], bf[nj][2], bf[nj][3], addr);
            }
#pragma unroll
            for (int nj = 0; nj < 4; nj++)
#pragma unroll
                for (int hh = 0; hh < 2; hh++) {
                    const int ni = nj * 2 + hh;
#pragma unroll
                    for (int mi = 0; mi < 2; mi++)
                        MMA16816(acc[mi][ni], a[mi], bf[nj][hh], bf[nj][hh + 2]);
                }
        }
    }

#pragma unroll
    for (int mi = 0; mi < 2; mi++)
#pragma unroll
        for (int ni = 0; ni < 8; ni++) {
            int row = m0 + wm * 32 + mi * 16 + g;
            int col = n0 + wn * 64 + ni * 8 + 2 * t4;
            float b0 = 0.f, b1 = 0.f;
            if (bias1) { b0 = bias1[col]; b1 = bias1[col + 1]; }
            if (bias2) { b0 += bias2[col]; b1 += bias2[col + 1]; }
            float v00 = acc[mi][ni][0] + b0, v01 = acc[mi][ni][1] + b1;
            float v10 = acc[mi][ni][2] + b0, v11 = acc[mi][ni][3] + b1;
            if (C) {
                *(float2*)&C[(size_t)row * ldc + col]       = make_float2(v00, v01);
                *(float2*)&C[(size_t)(row + 8) * ldc + col] = make_float2(v10, v11);
            }
            if (Chi) {
                __nv_bfloat16 h0,l0,h1,l1,h2,l2,h3,l3;
                split2(v00,h0,l0); split2(v01,h1,l1);
                split2(v10,h2,l2); split2(v11,h3,l3);
                *(__nv_bfloat162*)&Chi[(size_t)row * ldc + col]       = __nv_bfloat162(h0,h1);
                *(__nv_bfloat162*)&Clo[(size_t)row * ldc + col]       = __nv_bfloat162(l0,l1);
                *(__nv_bfloat162*)&Chi[(size_t)(row + 8) * ldc + col] = __nv_bfloat162(h2,h3);
                *(__nv_bfloat162*)&Clo[(size_t)(row + 8) * ldc + col] = __nv_bfloat162(l2,l3);
            }
        }
}

// ===========================================================================
// Attention scores via mma (unchanged, passing)
// ===========================================================================
__global__ void __launch_bounds__(256, 2) attn_scores_mma(const int* __restrict__ mask)
{
    extern __shared__ char smem[];
    const uint32_t sbase = smem_u32(smem);
    const int tid  = threadIdx.x;
    const int lane = tid & 31;
    const int warp = tid >> 5;
    const int wm   = warp >> 1, wn = warp & 1;
    const int g    = lane >> 2, t4 = lane & 3;
    const int m0   = blockIdx.x * 128;
    const int n0   = blockIdx.y * 128;
    const int z    = blockIdx.z;
    const int b    = z >> 3, h = z & 7;

    const size_t aoff = ((size_t)b * S_)   * H_ + h * HD_;
    const size_t boff = ((size_t)b * SKV_) * H_ + h * HD_;

    float acc[2][8][4];
#pragma unroll
    for (int mi = 0; mi < 2; mi++)
#pragma unroll
        for (int ni = 0; ni < 8; ni++)
#pragma unroll
            for (int f = 0; f < 4; f++) acc[mi][ni][f] = 0.f;

    const int c0r = (tid)       >> 2, c0k = ((tid)       & 3) * 8;
    const int c1r = (tid + 256) >> 2, c1k = ((tid + 256) & 3) * 8;

    const int lm_row = lane & 15;
    const int lm_col = (lane >> 4) * 16;

    auto issue = [&](int t, int buf) {
        const int seg  = t >> 1;
        const int kofs = (t & 1) * 32;
        const __nv_bfloat16* Ap = (seg < 2)  ? g_Qhi : g_Qlo;
        const __nv_bfloat16* Bp = (seg == 1) ? g_Klo : g_Khi;
        const uint32_t sA = sbase + buf * LGS_STAGE;
        const uint32_t sB = sA + LGS_BOFF;
        CP_ASYNC16(sA + c0r * 80 + c0k * 2, Ap + aoff + (size_t)(m0 + c0r) * H_ + kofs + c0k);
        CP_ASYNC16(sA + c1r * 80 + c1k * 2, Ap + aoff + (size_t)(m0 + c1r) * H_ + kofs + c1k);
        CP_ASYNC16(sB + c0r * 80 + c0k * 2, Bp + boff + (size_t)(n0 + c0r) * H_ + kofs + c0k);
        CP_ASYNC16(sB + c1r * 80 + c1k * 2, Bp + boff + (size_t)(n0 + c1r) * H_ + kofs + c1k);
    };

    issue(0, 0); CP_COMMIT();
    issue(1, 1); CP_COMMIT();
    issue(2, 2); CP_COMMIT();

    for (int t = 0; t < 6; t++) {
        if (t + 2 < 6)      { CP_WAIT2(); }
        else if (t + 1 < 6) { CP_WAIT1(); }
        else                { CP_WAIT0(); }
        __syncthreads();
        if (t + 3 < 6) { issue(t + 3, (t + 3) & 3); CP_COMMIT(); }

        const uint32_t sA = sbase + (t & 3) * LGS_STAGE;
        const uint32_t sB = sA + LGS_BOFF;

#pragma unroll
        for (int k0 = 0; k0 < 2; k0++) {
            const uint32_t kb = k0 * 32 + lm_col;
            uint32_t a[2][4];
#pragma unroll
            for (int mi = 0; mi < 2; mi++) {
                uint32_t addr = sA + (uint32_t)(wm * 32 + mi * 16 + lm_row) * 80 + kb;
                LDMATRIX_X4(a[mi][0], a[mi][1], a[mi][2], a[mi][3], addr);
            }
            uint32_t bf[4][4];
#pragma unroll
            for (int nj = 0; nj < 4; nj++) {
                uint32_t addr = sB + (uint32_t)(wn * 64 + nj * 16 + lm_row) * 80 + kb;
                LDMATRIX_X4(bf[nj][0], bf[nj][1], bf[nj][2], bf[nj][3], addr);
            }
#pragma unroll
            for (int nj = 0; nj < 4; nj++)
#pragma unroll
                for (int hh = 0; hh < 2; hh++) {
                    const int ni = nj * 2 + hh;
#pragma unroll
                    for (int mi = 0; mi < 2; mi++)
                        MMA16816(acc[mi][ni], a[mi], bf[nj][hh], bf[nj][hh + 2]);
                }
        }
    }

    const float scale = 0.125f;
#pragma unroll
    for (int mi = 0; mi < 2; mi++)
#pragma unroll
        for (int ni = 0; ni < 8; ni++) {
            int row = m0 + wm * 32 + mi * 16 + g;
            int col = n0 + wn * 64 + ni * 8 + 2 * t4;
            bool ok0 = mask[b * SKV_ + col]     == 1;
            bool ok1 = mask[b * SKV_ + col + 1] == 1;
            float2 v0 = make_float2(ok0 ? acc[mi][ni][0]*scale : -1e9f,
                                    ok1 ? acc[mi][ni][1]*scale : -1e9f);
            float2 v1 = make_float2(ok0 ? acc[mi][ni][2]*scale : -1e9f,
                                    ok1 ? acc[mi][ni][3]*scale : -1e9f);
            *(float2*)&g_att[((size_t)z * S_ + row)     * SKV_ + col] = v0;
            *(float2*)&g_att[((size_t)z * S_ + row + 8) * SKV_ + col] = v1;
        }
}

// ===========================================================================
// Softmax -> bf16 hi/lo attention weights
// ===========================================================================
__global__ void __launch_bounds__(128) softmax_k()
{
    const size_t base = (size_t)blockIdx.x * SKV_;
    const int tid = threadIdx.x;
    float v[8];
    float mx = -1e30f;
#pragma unroll
    for (int i = 0; i < 8; i++) {
        v[i] = g_att[base + tid + i * 128];
        mx = fmaxf(mx, v[i]);
    }
    __shared__ float sm[4];
#pragma unroll
    for (int off = 16; off > 0; off >>= 1)
        mx = fmaxf(mx, __shfl_xor_sync(0xffffffffu, mx, off));
    if ((tid & 31) == 0) sm[tid >> 5] = mx;
    __syncthreads();
    mx = fmaxf(fmaxf(sm[0], sm[1]), fmaxf(sm[2], sm[3]));

    float sum = 0.f;
#pragma unroll
    for (int i = 0; i < 8; i++) { v[i] = expf(v[i] - mx); sum += v[i]; }
#pragma unroll
    for (int off = 16; off > 0; off >>= 1)
        sum += __shfl_xor_sync(0xffffffffu, sum, off);
    __syncthreads();
    if ((tid & 31) == 0) sm[tid >> 5] = sum;
    __syncthreads();
    sum = sm[0] + sm[1] + sm[2] + sm[3];
    const float inv = 1.f / sum;
#pragma unroll
    for (int i = 0; i < 8; i++) {
        float w = v[i] * inv;
        __nv_bfloat16 hh, ll;
        split2(w, hh, ll);
        g_atth[base + tid + i * 128] = hh;
        g_attl[base + tid + i * 128] = ll;
    }
}

// ===========================================================================
// V transpose + split
// ===========================================================================
__global__ void __launch_bounds__(256) vt_split_k()
{
    __shared__ float sm[32][33];
    const int c0 = blockIdx.x * 32;
    const int k0 = blockIdx.y * 32;
    const int b  = blockIdx.z;
    const int tx = threadIdx.x & 31, ty = threadIdx.x >> 5;

#pragma unroll
    for (int j = 0; j < 4; j++) {
        int k = ty + j * 8;
        sm[k][tx] = g_V[((size_t)b * SKV_ + k0 + k) * H_ + c0 + tx];
    }
    __syncthreads();
#pragma unroll
    for (int j = 0; j < 4; j++) {
        int c = ty + j * 8;
        float v = sm[tx][c];
        __nv_bfloat16 hh, ll;
        split2(v, hh, ll);
        size_t o = ((size_t)b * H_ + c0 + c) * SKV_ + k0 + tx;
        g_VThi[o] = hh;
        g_VTlo[o] = ll;
    }
}

// ===========================================================================
// attn @ V via mma -> ctx hi/lo. m-tile 64 rows -> grid (4, 64) = 256 CTAs.
// 8 warps (4m x 2n), warp tile 16x32. Stage = 64*80 (A) + 64*80 (B) = 10240.
// ===========================================================================
#define CTX_STAGE 10240
#define CTX_BOFF  5120
#define CTX_SMEM  (4 * CTX_STAGE)

__global__ void __launch_bounds__(256, 2) attn_ctx_mma()
{
    extern __shared__ char smem[];
    const uint32_t sbase = smem_u32(smem);
    const int tid  = threadIdx.x;
    const int lane = tid & 31;
    const int warp = tid >> 5;
    const int wm   = warp >> 1, wn = warp & 1;   // 4m x 2n, warp tile 16x32
    const int g    = lane >> 2, t4 = lane & 3;
    const int m0   = blockIdx.x * 64;
    const int z    = blockIdx.y;
    const int b    = z >> 3, h = z & 7;

    const size_t aoff = (size_t)z * S_ * SKV_;
    const size_t boff = ((size_t)b * H_ + h * HD_) * SKV_;

    float acc[4][4];
#pragma unroll
    for (int ni = 0; ni < 4; ni++)
#pragma unroll
        for (int f = 0; f < 4; f++) acc[ni][f] = 0.f;

    // A: 64 rows x 64B = 256 chunks (1/thread); B: same
    const int a0r = tid >> 2, a0k = (tid & 3) * 8;
    const int bro = tid >> 2, brk = (tid & 3) * 8;

    const int lm_row = lane & 15;
    const int lm_col = (lane >> 4) * 16;

    auto issue = [&](int t, int buf) {
        const int seg  = t >> 5;
        const int kofs = (t & 31) * 32;
        const __nv_bfloat16* Ap = (seg < 2)  ? g_atth : g_attl;
        const __nv_bfloat16* Bp = (seg == 1) ? g_VTlo : g_VThi;
        const uint32_t sA = sbase + buf * CTX_STAGE;
        const uint32_t sB = sA + CTX_BOFF;
        CP_ASYNC16(sA + a0r * 80 + a0k * 2, Ap + aoff + (size_t)(m0 + a0r) * SKV_ + kofs + a0k);
        CP_ASYNC16(sB + bro * 80 + brk * 2, Bp + boff + (size_t)bro * SKV_ + kofs + brk);
    };

    issue(0, 0); CP_COMMIT();
    issue(1, 1); CP_COMMIT();
    issue(2, 2); CP_COMMIT();

    for (int t = 0; t < 96; t++) {
        if (t < 94)       { CP_WAIT2(); }
        else if (t == 94) { CP_WAIT1(); }
        else              { CP_WAIT0(); }
        __syncthreads();
        if (t + 3 < 96) { issue(t + 3, (t + 3) & 3); CP_COMMIT(); }

        const uint32_t sA = sbase + (t & 3) * CTX_STAGE;
        const uint32_t sB = sA + CTX_BOFF;

#pragma unroll
        for (int k0 = 0; k0 < 2; k0++) {
            const uint32_t kb = k0 * 32 + lm_col;
            uint32_t a[4];
            {
                uint32_t addr = sA + (uint32_t)(wm * 16 + lm_row) * 80 + kb;
                LDMATRIX_X4(a[0], a[1], a[2], a[3], addr);
            }
            uint32_t bf[2][4];
#pragma unroll
            for (int nj = 0; nj < 2; nj++) {
                uint32_t addr = sB + (uint32_t)(wn * 32 + nj * 16 + lm_row) * 80 + kb;
                LDMATRIX_X4(bf[nj][0], bf[nj][1], bf[nj][2], bf[nj][3], addr);
            }
#pragma unroll
            for (int nj = 0; nj < 2; nj++)
#pragma unroll
                for (int hh = 0; hh < 2; hh++) {
                    const int ni = nj * 2 + hh;
                    MMA16816(acc[ni], a, bf[nj][hh], bf[nj][hh + 2]);
                }
        }
    }

#pragma unroll
    for (int ni = 0; ni < 4; ni++) {
        int row = m0 + wm * 16 + g;
        int col = wn * 32 + ni * 8 + 2 * t4;
        __nv_bfloat16 h0,l0,h1,l1,h2,l2,h3,l3;
        split2(acc[ni][0],h0,l0); split2(acc[ni][1],h1,l1);
        split2(acc[ni][2],h2,l2); split2(acc[ni][3],h3,l3);
        size_t o0 = ((size_t)b * S_ + row)     * H_ + h * HD_ + col;
        size_t o1 = ((size_t)b * S_ + row + 8) * H_ + h * HD_ + col;
        *(__nv_bfloat162*)&g_ctxhi[o0] = __nv_bfloat162(h0,h1);
        *(__nv_bfloat162*)&g_ctxlo[o0] = __nv_bfloat162(l0,l1);
        *(__nv_bfloat162*)&g_ctxhi[o1] = __nv_bfloat162(h2,h3);
        *(__nv_bfloat162*)&g_ctxlo[o1] = __nv_bfloat162(l2,l3);
    }
}

// ===========================================================================
// Reset kernel: zero the 128 per-CTA recurrence flags
// ===========================================================================
__global__ void reset_k()
{
    if (threadIdx.x < 128) g_flags[threadIdx.x] = 0u;
}

// ===========================================================================
// Persistent LSTM recurrence — release-store flags + nanosleep-throttled poll
// ===========================================================================
__device__ __forceinline__ float sigm(float x) { return 1.f / (1.f + expf(-x)); }

__global__ void __launch_bounds__(256, 1) rnn_kernel(
    const float* __restrict__ W_hh, const float* __restrict__ h0,
    const float* __restrict__ c0)
{
    const int cta  = blockIdx.x;
    const int pair = cta >> 5;
    const int grp  = cta & 31;
    const int tid  = threadIdx.x;
    const int q    = tid >> 6;
    const int r    = tid & 63;
    const int gate = r >> 4, uu = r & 15;
    const int unit = grp * 16 + uu;

    __shared__ float h_sm[2][H_];
    __shared__ float red[4][64][2];
    __shared__ float gsm[64][2];
    __shared__ float c_sm[2][16];

    float w[128];
    {
        const float4* wp = (const float4*)(W_hh + (size_t)(gate * H_ + unit) * H_ + q * 128);
#pragma unroll
        for (int j = 0; j < 32; j++) {
            float4 v = wp[j];
            w[4*j+0] = v.x; w[4*j+1] = v.y; w[4*j+2] = v.z; w[4*j+3] = v.w;
        }
    }

    for (int s = 0; s < S_; s++) {
        {
            const int bb = tid >> 7, off = (tid & 127) * 4;
            float4 v;
            if (s == 0) v = *(const float4*)(h0 + (size_t)(pair*2 + bb) * H_ + off);
            else        v = __ldcg((const float4*)(g_hcur + (size_t)(pair*2 + bb) * H_ + off));
            *(float4*)&h_sm[bb][off] = v;
        }
        if (s == 0 && tid < 32) {
            int b2 = tid >> 4, u2 = tid & 15;
            c_sm[b2][u2] = c0[(size_t)(pair*2 + b2) * H_ + grp*16 + u2];
        }
        __syncthreads();

        float a0 = 0.f, a1 = 0.f;
        {
            const float* hp0 = &h_sm[0][q * 128];
            const float* hp1 = &h_sm[1][q * 128];
#pragma unroll
            for (int j = 0; j < 128; j++) {
                a0 += w[j] * hp0[j];
                a1 += w[j] * hp1[j];
            }
        }
        red[q][r][0] = a0;
        red[q][r][1] = a1;
        __syncthreads();

        if (tid < 128) {
            const int rr = tid >> 1, bb = tid & 1;
            const int gg = rr >> 4, u2 = rr & 15;
            float g = red[0][rr][bb] + red[1][rr][bb] + red[2][rr][bb] + red[3][rr][bb]
                    + g_xg[((size_t)(pair*2 + bb) * S_ + s) * G4_ + gg * H_ + grp*16 + u2];
            gsm[rr][bb] = g;
        }
        __syncthreads();

        if (tid < 32) {
            const int bb = tid >> 4, u2 = tid & 15;
            float iv = gsm[ 0 + u2][bb];
            float fv = gsm[16 + u2][bb];
            float gv = gsm[32 + u2][bb];
            float ov = gsm[48 + u2][bb];
            float cn = sigm(fv) * c_sm[bb][u2] + sigm(iv) * tanhf(gv);
            float hn = sigm(ov) * tanhf(cn);
            c_sm[bb][u2] = cn;
            const int bg = pair*2 + bb, un = grp*16 + u2;
            g_hcur[(size_t)bg * H_ + un] = hn;
            g_H[((size_t)bg * S_ + s) * H_ + un] = hn;
            __threadfence();
        }
        __syncthreads();

        // ---- barrier: parallel release-store arrival, throttled polling ----
        if (tid == 0) {
            asm volatile("st.release.gpu.global.u32 [%0], %1;"
                         :: "l"(&g_flags[cta]), "r"((unsigned)(s + 1))
                         : "memory");
        }
        if (tid < 32) {
            const unsigned* fp = &g_flags[pair * 32 + tid];
            unsigned v;
            while (true) {
                asm volatile("ld.global.cg.u32 %0, [%1];"
                             : "=r"(v) : "l"(fp) : "memory");
                if (v >= (unsigned)(s + 1)) break;
                __nanosleep(60);
            }
        }
        __syncthreads();
        __threadfence();
    }
}

// ===========================================================================
// Host orchestration
// ===========================================================================
extern "C" void kernel_launch(void* const* d_in, const int* in_sizes, int n_in,
                              void* d_out, int out_size)
{
    const int*   tok   = (const int*)  d_in[0];
    const float* enc   = (const float*)d_in[1];
    const int*   mask  = (const int*)  d_in[2];
    const float* emb   = (const float*)d_in[3];
    const float* W_ih  = (const float*)d_in[4];
    const float* W_hh  = (const float*)d_in[5];
    const float* b_ih  = (const float*)d_in[6];
    const float* b_hh  = (const float*)d_in[7];
    const float* Wq    = (const float*)d_in[8];
    const float* bq    = (const float*)d_in[9];
    const float* Wk    = (const float*)d_in[10];
    const float* bk    = (const float*)d_in[11];
    const float* Wv    = (const float*)d_in[12];
    const float* bv    = (const float*)d_in[13];
    const float* Wo    = (const float*)d_in[14];
    const float* bo    = (const float*)d_in[15];
    const float* h0    = (const float*)d_in[16];
    const float* c0    = (const float*)d_in[17];
    float* out = (float*)d_out;

    float *p_xg, *p_V, *p_H;
    cudaGetSymbolAddress((void**)&p_xg, g_xg);
    cudaGetSymbolAddress((void**)&p_V,  g_V);
    cudaGetSymbolAddress((void**)&p_H,  g_H);

    __nv_bfloat16 *p_ehi, *p_elo, *p_ohi, *p_olo, *p_echi, *p_eclo;
    __nv_bfloat16 *p_wihhi, *p_wihlo, *p_wqhi, *p_wqlo, *p_wkhi, *p_wklo;
    __nv_bfloat16 *p_wvhi, *p_wvlo, *p_wohi, *p_wolo;
    __nv_bfloat16 *p_Hhi, *p_Hlo, *p_cxhi, *p_cxlo, *p_Qhi, *p_Qlo, *p_Khi, *p_Klo;
    cudaGetSymbolAddress((void**)&p_ehi,   g_embhi);
    cudaGetSymbolAddress((void**)&p_elo,   g_emblo);
    cudaGetSymbolAddress((void**)&p_ohi,   g_outhi);
    cudaGetSymbolAddress((void**)&p_olo,   g_outlo);
    cudaGetSymbolAddress((void**)&p_echi,  g_enchi);
    cudaGetSymbolAddress((void**)&p_eclo,  g_enclo);
    cudaGetSymbolAddress((void**)&p_wihhi, g_wihhi);
    cudaGetSymbolAddress((void**)&p_wihlo, g_wihlo);
    cudaGetSymbolAddress((void**)&p_wqhi,  g_wqhi);
    cudaGetSymbolAddress((void**)&p_wqlo,  g_wqlo);
    cudaGetSymbolAddress((void**)&p_wkhi,  g_wkhi);
    cudaGetSymbolAddress((void**)&p_wklo,  g_wklo);
    cudaGetSymbolAddress((void**)&p_wvhi,  g_wvhi);
    cudaGetSymbolAddress((void**)&p_wvlo,  g_wvlo);
    cudaGetSymbolAddress((void**)&p_wohi,  g_wohi);
    cudaGetSymbolAddress((void**)&p_wolo,  g_wolo);
    cudaGetSymbolAddress((void**)&p_Hhi,   g_Hhi);
    cudaGetSymbolAddress((void**)&p_Hlo,   g_Hlo);
    cudaGetSymbolAddress((void**)&p_cxhi,  g_ctxhi);
    cudaGetSymbolAddress((void**)&p_cxlo,  g_ctxlo);
    cudaGetSymbolAddress((void**)&p_Qhi,   g_Qhi);
    cudaGetSymbolAddress((void**)&p_Qlo,   g_Qlo);
    cudaGetSymbolAddress((void**)&p_Khi,   g_Khi);
    cudaGetSymbolAddress((void**)&p_Klo,   g_Klo);

    cudaFuncSetAttribute(hgemm_tn_mma,
                         cudaFuncAttributeMaxDynamicSharedMemorySize, LGS_SMEM);
    cudaFuncSetAttribute(attn_scores_mma,
                         cudaFuncAttributeMaxDynamicSharedMemorySize, LGS_SMEM);
    cudaFuncSetAttribute(attn_ctx_mma,
                         cudaFuncAttributeMaxDynamicSharedMemorySize, CTX_SMEM);

    reset_k<<<1, 128>>>();

    // ---- input splits ----
    split_bf16_k<<<(V_*H_/4 + 1023)/1024, 256>>>(emb,  p_ehi,   p_elo,   V_*H_/4);
    split_bf16_k<<<(BKV_*H_/4 + 1023)/1024, 256>>>(enc, p_echi, p_eclo, BKV_*H_/4);
    split_bf16_k<<<(G4_*H_/4 + 1023)/1024, 256>>>(W_ih, p_wihhi, p_wihlo, G4_*H_/4);
    split_bf16_k<<<(H_*H_/4 + 1023)/1024, 256>>>(Wq,   p_wqhi,  p_wqlo,  H_*H_/4);
    split_bf16_k<<<(H_*H_/4 + 1023)/1024, 256>>>(Wk,   p_wkhi,  p_wklo,  H_*H_/4);
    split_bf16_k<<<(H_*H_/4 + 1023)/1024, 256>>>(Wv,   p_wvhi,  p_wvlo,  H_*H_/4);
    split_bf16_k<<<(H_*H_/4 + 1023)/1024, 256>>>(Wo,   p_wohi,  p_wolo,  H_*H_/4);

    // ---- x-gates (gather, fp32 out for rnn) ----
    hgemm_tn_mma<<<dim3(BT_/128, G4_/128), 256, LGS_SMEM>>>(
        G4_, p_ehi, p_elo, tok, p_wihhi, p_wihlo, b_ih, b_hh,
        p_xg, nullptr, nullptr);
    // ---- K projection -> bf16 hi/lo directly ----
    hgemm_tn_mma<<<dim3(BKV_/128, H_/128), 256, LGS_SMEM>>>(
        H_, p_echi, p_eclo, nullptr, p_wkhi, p_wklo, bk, nullptr,
        nullptr, p_Khi, p_Klo);
    // ---- V projection (fp32 out for the transpose) ----
    hgemm_tn_mma<<<dim3(BKV_/128, H_/128), 256, LGS_SMEM>>>(
        H_, p_echi, p_eclo, nullptr, p_wvhi, p_wvlo, bv, nullptr,
        p_V, nullptr, nullptr);
    vt_split_k<<<dim3(H_/32, SKV_/32, B_), 256>>>();

    // ---- serial LSTM recurrence ----
    rnn_kernel<<<128, 256>>>(W_hh, h0, c0);

    // ---- Q projection -> bf16 hi/lo directly ----
    split_bf16_k<<<(BT_*H_/4 + 1023)/1024, 256>>>(p_H, p_Hhi, p_Hlo, BT_*H_/4);
    hgemm_tn_mma<<<dim3(BT_/128, H_/128), 256, LGS_SMEM>>>(
        H_, p_Hhi, p_Hlo, nullptr, p_wqhi, p_wqlo, bq, nullptr,
        nullptr, p_Qhi, p_Qlo);

    // ---- attention ----
    attn_scores_mma<<<dim3(2, 8, 64), 256, LGS_SMEM>>>(mask);
    softmax_k<<<B_*NH_*S_, 128>>>();
    attn_ctx_mma<<<dim3(4, 64), 256, CTX_SMEM>>>();

    // ---- output projection -> bf16 hi/lo directly ----
    hgemm_tn_mma<<<dim3(BT_/128, H_/128), 256, LGS_SMEM>>>(
        H_, p_cxhi, p_cxlo, nullptr, p_wohi, p_wolo, bo, nullptr,
        nullptr, p_ohi, p_olo);

    // ---- tied logits ----
    hgemm_tn_mma<<<dim3(BT_/128, V_/128), 256, LGS_SMEM>>>(
        V_, p_ohi, p_olo, nullptr, p_ehi, p_elo, nullptr, nullptr,
        out, nullptr, nullptr);
}

// round 17
// speedup vs baseline: 1.4760x; 1.4760x over previous
#include <cuda_runtime.h>
#include <cuda_bf16.h>
#include <math.h>
#include <cstdint>

// ---------------- problem constants ----------------
#define B_    8
#define S_    256
#define SKV_  1024
#define H_    512
#define NH_   8
#define HD_   64
#define G4_   2048
#define V_    32000
#define BT_   (B_*S_)         // 2048
#define BKV_  (B_*SKV_)       // 8192
#define K_GEMM 512

// ---------------- device scratch ----------------
__device__ float    g_xg  [BT_  * (size_t)G4_];
__device__ float    g_V   [BKV_ * (size_t)H_];
__device__ float    g_H   [BT_  * (size_t)H_];
__device__ float    g_hcur[B_ * H_];
__device__ float    g_att [(size_t)B_ * NH_ * S_ * SKV_];
__device__ unsigned g_arrive[4];
// split-bf16 operand buffers
__device__ __nv_bfloat16 g_embhi[(size_t)V_ * H_];
__device__ __nv_bfloat16 g_emblo[(size_t)V_ * H_];
__device__ __nv_bfloat16 g_outhi[(size_t)BT_ * H_];
__device__ __nv_bfloat16 g_outlo[(size_t)BT_ * H_];
__device__ __nv_bfloat16 g_enchi[(size_t)BKV_ * H_];
__device__ __nv_bfloat16 g_enclo[(size_t)BKV_ * H_];
__device__ __nv_bfloat16 g_wihhi[(size_t)G4_ * H_];
__device__ __nv_bfloat16 g_wihlo[(size_t)G4_ * H_];
__device__ __nv_bfloat16 g_wqhi[(size_t)H_ * H_];
__device__ __nv_bfloat16 g_wqlo[(size_t)H_ * H_];
__device__ __nv_bfloat16 g_wkhi[(size_t)H_ * H_];
__device__ __nv_bfloat16 g_wklo[(size_t)H_ * H_];
__device__ __nv_bfloat16 g_wvhi[(size_t)H_ * H_];
__device__ __nv_bfloat16 g_wvlo[(size_t)H_ * H_];
__device__ __nv_bfloat16 g_wohi[(size_t)H_ * H_];
__device__ __nv_bfloat16 g_wolo[(size_t)H_ * H_];
__device__ __nv_bfloat16 g_Hhi [(size_t)BT_ * H_];
__device__ __nv_bfloat16 g_Hlo [(size_t)BT_ * H_];
__device__ __nv_bfloat16 g_ctxhi[(size_t)BT_ * H_];
__device__ __nv_bfloat16 g_ctxlo[(size_t)BT_ * H_];
// attention operands
__device__ __nv_bfloat16 g_Qhi [(size_t)BT_ * H_];
__device__ __nv_bfloat16 g_Qlo [(size_t)BT_ * H_];
__device__ __nv_bfloat16 g_Khi [(size_t)BKV_ * H_];
__device__ __nv_bfloat16 g_Klo [(size_t)BKV_ * H_];
__device__ __nv_bfloat16 g_atth[(size_t)B_ * NH_ * S_ * SKV_];
__device__ __nv_bfloat16 g_attl[(size_t)B_ * NH_ * S_ * SKV_];
__device__ __nv_bfloat16 g_VThi[(size_t)B_ * H_ * SKV_];
__device__ __nv_bfloat16 g_VTlo[(size_t)B_ * H_ * SKV_];

// ---------------- helpers ----------------
#define CP_ASYNC16(dst, src) \
    asm volatile("cp.async.cg.shared.global [%0], [%1], 16;" :: "r"(dst), "l"(src))
#define CP_COMMIT() asm volatile("cp.async.commit_group;" ::: "memory")
#define CP_WAIT0()  asm volatile("cp.async.wait_group 0;" ::: "memory")
#define CP_WAIT1()  asm volatile("cp.async.wait_group 1;" ::: "memory")
#define CP_WAIT2()  asm volatile("cp.async.wait_group 2;" ::: "memory")

__device__ __forceinline__ uint32_t smem_u32(const void* p) {
    uint32_t a;
    asm("{ .reg .u64 t; cvta.to.shared.u64 t, %1; cvt.u32.u64 %0, t; }"
        : "=r"(a) : "l"(p));
    return a;
}
#define LDMATRIX_X4(r0, r1, r2, r3, addr) \
    asm volatile("ldmatrix.sync.aligned.m8n8.x4.shared.b16 {%0,%1,%2,%3}, [%4];" \
        : "=r"(r0), "=r"(r1), "=r"(r2), "=r"(r3) : "r"(addr))
#define MMA16816(acc, a, b0v, b1v) \
    asm volatile( \
        "mma.sync.aligned.m16n8k16.row.col.f32.bf16.bf16.f32 " \
        "{%0,%1,%2,%3}, {%4,%5,%6,%7}, {%8,%9}, {%0,%1,%2,%3};\n" \
        : "+f"((acc)[0]), "+f"((acc)[1]), "+f"((acc)[2]), "+f"((acc)[3]) \
        : "r"((a)[0]), "r"((a)[1]), "r"((a)[2]), "r"((a)[3]), "r"(b0v), "r"(b1v))

__device__ __forceinline__ void split2(float v, __nv_bfloat16& h, __nv_bfloat16& l) {
    h = __float2bfloat16(v);
    l = __float2bfloat16(v - __bfloat162float(h));
}

// ===========================================================================
// fp32 -> (bf16 hi, bf16 lo) split
// ===========================================================================
__global__ void __launch_bounds__(256) split_bf16_k(
    const float* __restrict__ x, __nv_bfloat16* __restrict__ hi,
    __nv_bfloat16* __restrict__ lo, int n4)
{
    int base = blockIdx.x * 1024 + threadIdx.x;
    float4 v[4];
    bool p[4];
#pragma unroll
    for (int j = 0; j < 4; j++) {
        int idx = base + j * 256;
        p[j] = idx < n4;
        if (p[j]) v[j] = ((const float4*)x)[idx];
    }
#pragma unroll
    for (int j = 0; j < 4; j++) {
        if (!p[j]) continue;
        int idx = base + j * 256;
        __nv_bfloat16 h0,h1,h2,h3,l0,l1,l2,l3;
        split2(v[j].x,h0,l0); split2(v[j].y,h1,l1);
        split2(v[j].z,h2,l2); split2(v[j].w,h3,l3);
        __nv_bfloat162* hp = (__nv_bfloat162*)(hi + (size_t)idx * 4);
        __nv_bfloat162* lp = (__nv_bfloat162*)(lo + (size_t)idx * 4);
        hp[0] = __nv_bfloat162(h0,h1); hp[1] = __nv_bfloat162(h2,h3);
        lp[0] = __nv_bfloat162(l0,l1); lp[1] = __nv_bfloat162(l2,l3);
    }
}

// ===========================================================================
// Dense split-bf16 TN GEMM with optional epilogue-fused bf16 hi/lo output
// ===========================================================================
#define LGS_STAGE  20480
#define LGS_BOFF   10240
#define LGS_SMEM   (4 * LGS_STAGE)

__global__ void __launch_bounds__(256, 2) hgemm_tn_mma(
    int ldc,
    const __nv_bfloat16* __restrict__ Ahi, const __nv_bfloat16* __restrict__ Alo,
    const int* __restrict__ gidx,
    const __nv_bfloat16* __restrict__ Bhi, const __nv_bfloat16* __restrict__ Blo,
    const float* __restrict__ bias1, const float* __restrict__ bias2,
    float* __restrict__ C,
    __nv_bfloat16* __restrict__ Chi, __nv_bfloat16* __restrict__ Clo)
{
    extern __shared__ char smem[];
    const uint32_t sbase = smem_u32(smem);
    const int tid  = threadIdx.x;
    const int lane = tid & 31;
    const int warp = tid >> 5;
    const int wm   = warp >> 1, wn = warp & 1;
    const int g    = lane >> 2, t4 = lane & 3;
    const int m0   = blockIdx.x * 128;
    const int n0   = blockIdx.y * 128;

    float acc[2][8][4];
#pragma unroll
    for (int mi = 0; mi < 2; mi++)
#pragma unroll
        for (int ni = 0; ni < 8; ni++)
#pragma unroll
            for (int f = 0; f < 4; f++) acc[mi][ni][f] = 0.f;

    const int c0r = (tid)       >> 2, c0k = ((tid)       & 3) * 8;
    const int c1r = (tid + 256) >> 2, c1k = ((tid + 256) & 3) * 8;
    int ar0 = m0 + c0r, ar1 = m0 + c1r;
    if (gidx) { ar0 = gidx[ar0]; ar1 = gidx[ar1]; }
    const int br0 = n0 + c0r, br1 = n0 + c1r;

    const int lm_row = lane & 15;
    const int lm_col = (lane >> 4) * 16;

    auto issue = [&](int t, int buf) {
        const int seg  = t >> 4;
        const int kofs = (t & 15) * 32;
        const __nv_bfloat16* Ap = (seg < 2)  ? Ahi : Alo;
        const __nv_bfloat16* Bp = (seg == 1) ? Blo : Bhi;
        const uint32_t sA = sbase + buf * LGS_STAGE;
        const uint32_t sB = sA + LGS_BOFF;
        CP_ASYNC16(sA + c0r * 80 + c0k * 2, Ap + (size_t)ar0 * K_GEMM + kofs + c0k);
        CP_ASYNC16(sA + c1r * 80 + c1k * 2, Ap + (size_t)ar1 * K_GEMM + kofs + c1k);
        CP_ASYNC16(sB + c0r * 80 + c0k * 2, Bp + (size_t)br0 * K_GEMM + kofs + c0k);
        CP_ASYNC16(sB + c1r * 80 + c1k * 2, Bp + (size_t)br1 * K_GEMM + kofs + c1k);
    };

    issue(0, 0); CP_COMMIT();
    issue(1, 1); CP_COMMIT();
    issue(2, 2); CP_COMMIT();

    for (int t = 0; t < 48; t++) {
        if (t < 46)       { CP_WAIT2(); }
        else if (t == 46) { CP_WAIT1(); }
        else              { CP_WAIT0(); }
        __syncthreads();
        if (t + 3 < 48) { issue(t + 3, (t + 3) & 3); CP_COMMIT(); }

        const uint32_t sA = sbase + (t & 3) * LGS_STAGE;
        const uint32_t sB = sA + LGS_BOFF;

#pragma unroll
        for (int k0 = 0; k0 < 2; k0++) {
            const uint32_t kb = k0 * 32 + lm_col;
            uint32_t a[2][4];
#pragma unroll
            for (int mi = 0; mi < 2; mi++) {
                uint32_t addr = sA + (uint32_t)(wm * 32 + mi * 16 + lm_row) * 80 + kb;
                LDMATRIX_X4(a[mi][0], a[mi][1], a[mi][2], a[mi][3], addr);
            }
            uint32_t bf[4][4];
#pragma unroll
            for (int nj = 0; nj < 4; nj++) {
                uint32_t addr = sB + (uint32_t)(wn * 64 + nj * 16 + lm_row) * 80 + kb;
                LDMATRIX_X4(bf[nj][0], bf[nj][1], bf[nj][2], bf[nj][3], addr);
            }
#pragma unroll
            for (int nj = 0; nj < 4; nj++)
#pragma unroll
                for (int hh = 0; hh < 2; hh++) {
                    const int ni = nj * 2 + hh;
#pragma unroll
                    for (int mi = 0; mi < 2; mi++)
                        MMA16816(acc[mi][ni], a[mi], bf[nj][hh], bf[nj][hh + 2]);
                }
        }
    }

#pragma unroll
    for (int mi = 0; mi < 2; mi++)
#pragma unroll
        for (int ni = 0; ni < 8; ni++) {
            int row = m0 + wm * 32 + mi * 16 + g;
            int col = n0 + wn * 64 + ni * 8 + 2 * t4;
            float b0 = 0.f, b1 = 0.f;
            if (bias1) { b0 = bias1[col]; b1 = bias1[col + 1]; }
            if (bias2) { b0 += bias2[col]; b1 += bias2[col + 1]; }
            float v00 = acc[mi][ni][0] + b0, v01 = acc[mi][ni][1] + b1;
            float v10 = acc[mi][ni][2] + b0, v11 = acc[mi][ni][3] + b1;
            if (C) {
                *(float2*)&C[(size_t)row * ldc + col]       = make_float2(v00, v01);
                *(float2*)&C[(size_t)(row + 8) * ldc + col] = make_float2(v10, v11);
            }
            if (Chi) {
                __nv_bfloat16 h0,l0,h1,l1,h2,l2,h3,l3;
                split2(v00,h0,l0); split2(v01,h1,l1);
                split2(v10,h2,l2); split2(v11,h3,l3);
                *(__nv_bfloat162*)&Chi[(size_t)row * ldc + col]       = __nv_bfloat162(h0,h1);
                *(__nv_bfloat162*)&Clo[(size_t)row * ldc + col]       = __nv_bfloat162(l0,l1);
                *(__nv_bfloat162*)&Chi[(size_t)(row + 8) * ldc + col] = __nv_bfloat162(h2,h3);
                *(__nv_bfloat162*)&Clo[(size_t)(row + 8) * ldc + col] = __nv_bfloat162(l2,l3);
            }
        }
}

// ===========================================================================
// Attention scores via mma (unchanged, passing)
// ===========================================================================
__global__ void __launch_bounds__(256, 2) attn_scores_mma(const int* __restrict__ mask)
{
    extern __shared__ char smem[];
    const uint32_t sbase = smem_u32(smem);
    const int tid  = threadIdx.x;
    const int lane = tid & 31;
    const int warp = tid >> 5;
    const int wm   = warp >> 1, wn = warp & 1;
    const int g    = lane >> 2, t4 = lane & 3;
    const int m0   = blockIdx.x * 128;
    const int n0   = blockIdx.y * 128;
    const int z    = blockIdx.z;
    const int b    = z >> 3, h = z & 7;

    const size_t aoff = ((size_t)b * S_)   * H_ + h * HD_;
    const size_t boff = ((size_t)b * SKV_) * H_ + h * HD_;

    float acc[2][8][4];
#pragma unroll
    for (int mi = 0; mi < 2; mi++)
#pragma unroll
        for (int ni = 0; ni < 8; ni++)
#pragma unroll
            for (int f = 0; f < 4; f++) acc[mi][ni][f] = 0.f;

    const int c0r = (tid)       >> 2, c0k = ((tid)       & 3) * 8;
    const int c1r = (tid + 256) >> 2, c1k = ((tid + 256) & 3) * 8;

    const int lm_row = lane & 15;
    const int lm_col = (lane >> 4) * 16;

    auto issue = [&](int t, int buf) {
        const int seg  = t >> 1;
        const int kofs = (t & 1) * 32;
        const __nv_bfloat16* Ap = (seg < 2)  ? g_Qhi : g_Qlo;
        const __nv_bfloat16* Bp = (seg == 1) ? g_Klo : g_Khi;
        const uint32_t sA = sbase + buf * LGS_STAGE;
        const uint32_t sB = sA + LGS_BOFF;
        CP_ASYNC16(sA + c0r * 80 + c0k * 2, Ap + aoff + (size_t)(m0 + c0r) * H_ + kofs + c0k);
        CP_ASYNC16(sA + c1r * 80 + c1k * 2, Ap + aoff + (size_t)(m0 + c1r) * H_ + kofs + c1k);
        CP_ASYNC16(sB + c0r * 80 + c0k * 2, Bp + boff + (size_t)(n0 + c0r) * H_ + kofs + c0k);
        CP_ASYNC16(sB + c1r * 80 + c1k * 2, Bp + boff + (size_t)(n0 + c1r) * H_ + kofs + c1k);
    };

    issue(0, 0); CP_COMMIT();
    issue(1, 1); CP_COMMIT();
    issue(2, 2); CP_COMMIT();

    for (int t = 0; t < 6; t++) {
        if (t + 2 < 6)      { CP_WAIT2(); }
        else if (t + 1 < 6) { CP_WAIT1(); }
        else                { CP_WAIT0(); }
        __syncthreads();
        if (t + 3 < 6) { issue(t + 3, (t + 3) & 3); CP_COMMIT(); }

        const uint32_t sA = sbase + (t & 3) * LGS_STAGE;
        const uint32_t sB = sA + LGS_BOFF;

#pragma unroll
        for (int k0 = 0; k0 < 2; k0++) {
            const uint32_t kb = k0 * 32 + lm_col;
            uint32_t a[2][4];
#pragma unroll
            for (int mi = 0; mi < 2; mi++) {
                uint32_t addr = sA + (uint32_t)(wm * 32 + mi * 16 + lm_row) * 80 + kb;
                LDMATRIX_X4(a[mi][0], a[mi][1], a[mi][2], a[mi][3], addr);
            }
            uint32_t bf[4][4];
#pragma unroll
            for (int nj = 0; nj < 4; nj++) {
                uint32_t addr = sB + (uint32_t)(wn * 64 + nj * 16 + lm_row) * 80 + kb;
                LDMATRIX_X4(bf[nj][0], bf[nj][1], bf[nj][2], bf[nj][3], addr);
            }
#pragma unroll
            for (int nj = 0; nj < 4; nj++)
#pragma unroll
                for (int hh = 0; hh < 2; hh++) {
                    const int ni = nj * 2 + hh;
#pragma unroll
                    for (int mi = 0; mi < 2; mi++)
                        MMA16816(acc[mi][ni], a[mi], bf[nj][hh], bf[nj][hh + 2]);
                }
        }
    }

    const float scale = 0.125f;
#pragma unroll
    for (int mi = 0; mi < 2; mi++)
#pragma unroll
        for (int ni = 0; ni < 8; ni++) {
            int row = m0 + wm * 32 + mi * 16 + g;
            int col = n0 + wn * 64 + ni * 8 + 2 * t4;
            bool ok0 = mask[b * SKV_ + col]     == 1;
            bool ok1 = mask[b * SKV_ + col + 1] == 1;
            float2 v0 = make_float2(ok0 ? acc[mi][ni][0]*scale : -1e9f,
                                    ok1 ? acc[mi][ni][1]*scale : -1e9f);
            float2 v1 = make_float2(ok0 ? acc[mi][ni][2]*scale : -1e9f,
                                    ok1 ? acc[mi][ni][3]*scale : -1e9f);
            *(float2*)&g_att[((size_t)z * S_ + row)     * SKV_ + col] = v0;
            *(float2*)&g_att[((size_t)z * S_ + row + 8) * SKV_ + col] = v1;
        }
}

// ===========================================================================
// Softmax -> bf16 hi/lo attention weights
// ===========================================================================
__global__ void __launch_bounds__(128) softmax_k()
{
    const size_t base = (size_t)blockIdx.x * SKV_;
    const int tid = threadIdx.x;
    float v[8];
    float mx = -1e30f;
#pragma unroll
    for (int i = 0; i < 8; i++) {
        v[i] = g_att[base + tid + i * 128];
        mx = fmaxf(mx, v[i]);
    }
    __shared__ float sm[4];
#pragma unroll
    for (int off = 16; off > 0; off >>= 1)
        mx = fmaxf(mx, __shfl_xor_sync(0xffffffffu, mx, off));
    if ((tid & 31) == 0) sm[tid >> 5] = mx;
    __syncthreads();
    mx = fmaxf(fmaxf(sm[0], sm[1]), fmaxf(sm[2], sm[3]));

    float sum = 0.f;
#pragma unroll
    for (int i = 0; i < 8; i++) { v[i] = expf(v[i] - mx); sum += v[i]; }
#pragma unroll
    for (int off = 16; off > 0; off >>= 1)
        sum += __shfl_xor_sync(0xffffffffu, sum, off);
    __syncthreads();
    if ((tid & 31) == 0) sm[tid >> 5] = sum;
    __syncthreads();
    sum = sm[0] + sm[1] + sm[2] + sm[3];
    const float inv = 1.f / sum;
#pragma unroll
    for (int i = 0; i < 8; i++) {
        float w = v[i] * inv;
        __nv_bfloat16 hh, ll;
        split2(w, hh, ll);
        g_atth[base + tid + i * 128] = hh;
        g_attl[base + tid + i * 128] = ll;
    }
}

// ===========================================================================
// V transpose + split
// ===========================================================================
__global__ void __launch_bounds__(256) vt_split_k()
{
    __shared__ float sm[32][33];
    const int c0 = blockIdx.x * 32;
    const int k0 = blockIdx.y * 32;
    const int b  = blockIdx.z;
    const int tx = threadIdx.x & 31, ty = threadIdx.x >> 5;

#pragma unroll
    for (int j = 0; j < 4; j++) {
        int k = ty + j * 8;
        sm[k][tx] = g_V[((size_t)b * SKV_ + k0 + k) * H_ + c0 + tx];
    }
    __syncthreads();
#pragma unroll
    for (int j = 0; j < 4; j++) {
        int c = ty + j * 8;
        float v = sm[tx][c];
        __nv_bfloat16 hh, ll;
        split2(v, hh, ll);
        size_t o = ((size_t)b * H_ + c0 + c) * SKV_ + k0 + tx;
        g_VThi[o] = hh;
        g_VTlo[o] = ll;
    }
}

// ===========================================================================
// attn @ V via mma -> ctx hi/lo. m-tile 64 rows -> grid (4, 64) = 256 CTAs.
// ===========================================================================
#define CTX_STAGE 10240
#define CTX_BOFF  5120
#define CTX_SMEM  (4 * CTX_STAGE)

__global__ void __launch_bounds__(256, 2) attn_ctx_mma()
{
    extern __shared__ char smem[];
    const uint32_t sbase = smem_u32(smem);
    const int tid  = threadIdx.x;
    const int lane = tid & 31;
    const int warp = tid >> 5;
    const int wm   = warp >> 1, wn = warp & 1;   // 4m x 2n, warp tile 16x32
    const int g    = lane >> 2, t4 = lane & 3;
    const int m0   = blockIdx.x * 64;
    const int z    = blockIdx.y;
    const int b    = z >> 3, h = z & 7;

    const size_t aoff = (size_t)z * S_ * SKV_;
    const size_t boff = ((size_t)b * H_ + h * HD_) * SKV_;

    float acc[4][4];
#pragma unroll
    for (int ni = 0; ni < 4; ni++)
#pragma unroll
        for (int f = 0; f < 4; f++) acc[ni][f] = 0.f;

    const int a0r = tid >> 2, a0k = (tid & 3) * 8;
    const int bro = tid >> 2, brk = (tid & 3) * 8;

    const int lm_row = lane & 15;
    const int lm_col = (lane >> 4) * 16;

    auto issue = [&](int t, int buf) {
        const int seg  = t >> 5;
        const int kofs = (t & 31) * 32;
        const __nv_bfloat16* Ap = (seg < 2)  ? g_atth : g_attl;
        const __nv_bfloat16* Bp = (seg == 1) ? g_VTlo : g_VThi;
        const uint32_t sA = sbase + buf * CTX_STAGE;
        const uint32_t sB = sA + CTX_BOFF;
        CP_ASYNC16(sA + a0r * 80 + a0k * 2, Ap + aoff + (size_t)(m0 + a0r) * SKV_ + kofs + a0k);
        CP_ASYNC16(sB + bro * 80 + brk * 2, Bp + boff + (size_t)bro * SKV_ + kofs + brk);
    };

    issue(0, 0); CP_COMMIT();
    issue(1, 1); CP_COMMIT();
    issue(2, 2); CP_COMMIT();

    for (int t = 0; t < 96; t++) {
        if (t < 94)       { CP_WAIT2(); }
        else if (t == 94) { CP_WAIT1(); }
        else              { CP_WAIT0(); }
        __syncthreads();
        if (t + 3 < 96) { issue(t + 3, (t + 3) & 3); CP_COMMIT(); }

        const uint32_t sA = sbase + (t & 3) * CTX_STAGE;
        const uint32_t sB = sA + CTX_BOFF;

#pragma unroll
        for (int k0 = 0; k0 < 2; k0++) {
            const uint32_t kb = k0 * 32 + lm_col;
            uint32_t a[4];
            {
                uint32_t addr = sA + (uint32_t)(wm * 16 + lm_row) * 80 + kb;
                LDMATRIX_X4(a[0], a[1], a[2], a[3], addr);
            }
            uint32_t bf[2][4];
#pragma unroll
            for (int nj = 0; nj < 2; nj++) {
                uint32_t addr = sB + (uint32_t)(wn * 32 + nj * 16 + lm_row) * 80 + kb;
                LDMATRIX_X4(bf[nj][0], bf[nj][1], bf[nj][2], bf[nj][3], addr);
            }
#pragma unroll
            for (int nj = 0; nj < 2; nj++)
#pragma unroll
                for (int hh = 0; hh < 2; hh++) {
                    const int ni = nj * 2 + hh;
                    MMA16816(acc[ni], a, bf[nj][hh], bf[nj][hh + 2]);
                }
        }
    }

#pragma unroll
    for (int ni = 0; ni < 4; ni++) {
        int row = m0 + wm * 16 + g;
        int col = wn * 32 + ni * 8 + 2 * t4;
        __nv_bfloat16 h0,l0,h1,l1,h2,l2,h3,l3;
        split2(acc[ni][0],h0,l0); split2(acc[ni][1],h1,l1);
        split2(acc[ni][2],h2,l2); split2(acc[ni][3],h3,l3);
        size_t o0 = ((size_t)b * S_ + row)     * H_ + h * HD_ + col;
        size_t o1 = ((size_t)b * S_ + row + 8) * H_ + h * HD_ + col;
        *(__nv_bfloat162*)&g_ctxhi[o0] = __nv_bfloat162(h0,h1);
        *(__nv_bfloat162*)&g_ctxlo[o0] = __nv_bfloat162(l0,l1);
        *(__nv_bfloat162*)&g_ctxhi[o1] = __nv_bfloat162(h2,h3);
        *(__nv_bfloat162*)&g_ctxlo[o1] = __nv_bfloat162(l2,l3);
    }
}

// ===========================================================================
// Reset kernel
// ===========================================================================
__global__ void reset_k()
{
    if (threadIdx.x < 4) g_arrive[threadIdx.x] = 0u;
}

// ===========================================================================
// Persistent LSTM recurrence — proven atomicAdd barrier (R12/R15)
// ===========================================================================
__device__ __forceinline__ float sigm(float x) { return 1.f / (1.f + expf(-x)); }

__global__ void __launch_bounds__(256, 1) rnn_kernel(
    const float* __restrict__ W_hh, const float* __restrict__ h0,
    const float* __restrict__ c0)
{
    const int cta  = blockIdx.x;
    const int pair = cta >> 5;
    const int grp  = cta & 31;
    const int tid  = threadIdx.x;
    const int q    = tid >> 6;
    const int r    = tid & 63;
    const int gate = r >> 4, uu = r & 15;
    const int unit = grp * 16 + uu;

    __shared__ float h_sm[2][H_];
    __shared__ float red[4][64][2];
    __shared__ float gsm[64][2];
    __shared__ float c_sm[2][16];

    float w[128];
    {
        const float4* wp = (const float4*)(W_hh + (size_t)(gate * H_ + unit) * H_ + q * 128);
#pragma unroll
        for (int j = 0; j < 32; j++) {
            float4 v = wp[j];
            w[4*j+0] = v.x; w[4*j+1] = v.y; w[4*j+2] = v.z; w[4*j+3] = v.w;
        }
    }

    for (int s = 0; s < S_; s++) {
        {
            const int bb = tid >> 7, off = (tid & 127) * 4;
            float4 v;
            if (s == 0) v = *(const float4*)(h0 + (size_t)(pair*2 + bb) * H_ + off);
            else        v = __ldcg((const float4*)(g_hcur + (size_t)(pair*2 + bb) * H_ + off));
            *(float4*)&h_sm[bb][off] = v;
        }
        if (s == 0 && tid < 32) {
            int b2 = tid >> 4, u2 = tid & 15;
            c_sm[b2][u2] = c0[(size_t)(pair*2 + b2) * H_ + grp*16 + u2];
        }
        __syncthreads();

        float a0 = 0.f, a1 = 0.f;
        {
            const float* hp0 = &h_sm[0][q * 128];
            const float* hp1 = &h_sm[1][q * 128];
#pragma unroll
            for (int j = 0; j < 128; j++) {
                a0 += w[j] * hp0[j];
                a1 += w[j] * hp1[j];
            }
        }
        red[q][r][0] = a0;
        red[q][r][1] = a1;
        __syncthreads();

        if (tid < 128) {
            const int rr = tid >> 1, bb = tid & 1;
            const int gg = rr >> 4, u2 = rr & 15;
            float g = red[0][rr][bb] + red[1][rr][bb] + red[2][rr][bb] + red[3][rr][bb]
                    + g_xg[((size_t)(pair*2 + bb) * S_ + s) * G4_ + gg * H_ + grp*16 + u2];
            gsm[rr][bb] = g;
        }
        __syncthreads();

        if (tid < 32) {
            const int bb = tid >> 4, u2 = tid & 15;
            float iv = gsm[ 0 + u2][bb];
            float fv = gsm[16 + u2][bb];
            float gv = gsm[32 + u2][bb];
            float ov = gsm[48 + u2][bb];
            float cn = sigm(fv) * c_sm[bb][u2] + sigm(iv) * tanhf(gv);
            float hn = sigm(ov) * tanhf(cn);
            c_sm[bb][u2] = cn;
            const int bg = pair*2 + bb, un = grp*16 + u2;
            g_hcur[(size_t)bg * H_ + un] = hn;
            g_H[((size_t)bg * S_ + s) * H_ + un] = hn;
            __threadfence();
        }
        __syncthreads();

        if (tid == 0) {
            atomicAdd(&g_arrive[pair], 1u);
            const unsigned target = 32u * (unsigned)(s + 1);
            while (*((volatile unsigned*)&g_arrive[pair]) < target) { }
        }
        __syncthreads();
        __threadfence();
    }
}

// ===========================================================================
// Host orchestration
// ===========================================================================
extern "C" void kernel_launch(void* const* d_in, const int* in_sizes, int n_in,
                              void* d_out, int out_size)
{
    const int*   tok   = (const int*)  d_in[0];
    const float* enc   = (const float*)d_in[1];
    const int*   mask  = (const int*)  d_in[2];
    const float* emb   = (const float*)d_in[3];
    const float* W_ih  = (const float*)d_in[4];
    const float* W_hh  = (const float*)d_in[5];
    const float* b_ih  = (const float*)d_in[6];
    const float* b_hh  = (const float*)d_in[7];
    const float* Wq    = (const float*)d_in[8];
    const float* bq    = (const float*)d_in[9];
    const float* Wk    = (const float*)d_in[10];
    const float* bk    = (const float*)d_in[11];
    const float* Wv    = (const float*)d_in[12];
    const float* bv    = (const float*)d_in[13];
    const float* Wo    = (const float*)d_in[14];
    const float* bo    = (const float*)d_in[15];
    const float* h0    = (const float*)d_in[16];
    const float* c0    = (const float*)d_in[17];
    float* out = (float*)d_out;

    float *p_xg, *p_V, *p_H;
    cudaGetSymbolAddress((void**)&p_xg, g_xg);
    cudaGetSymbolAddress((void**)&p_V,  g_V);
    cudaGetSymbolAddress((void**)&p_H,  g_H);

    __nv_bfloat16 *p_ehi, *p_elo, *p_ohi, *p_olo, *p_echi, *p_eclo;
    __nv_bfloat16 *p_wihhi, *p_wihlo, *p_wqhi, *p_wqlo, *p_wkhi, *p_wklo;
    __nv_bfloat16 *p_wvhi, *p_wvlo, *p_wohi, *p_wolo;
    __nv_bfloat16 *p_Hhi, *p_Hlo, *p_cxhi, *p_cxlo, *p_Qhi, *p_Qlo, *p_Khi, *p_Klo;
    cudaGetSymbolAddress((void**)&p_ehi,   g_embhi);
    cudaGetSymbolAddress((void**)&p_elo,   g_emblo);
    cudaGetSymbolAddress((void**)&p_ohi,   g_outhi);
    cudaGetSymbolAddress((void**)&p_olo,   g_outlo);
    cudaGetSymbolAddress((void**)&p_echi,  g_enchi);
    cudaGetSymbolAddress((void**)&p_eclo,  g_enclo);
    cudaGetSymbolAddress((void**)&p_wihhi, g_wihhi);
    cudaGetSymbolAddress((void**)&p_wihlo, g_wihlo);
    cudaGetSymbolAddress((void**)&p_wqhi,  g_wqhi);
    cudaGetSymbolAddress((void**)&p_wqlo,  g_wqlo);
    cudaGetSymbolAddress((void**)&p_wkhi,  g_wkhi);
    cudaGetSymbolAddress((void**)&p_wklo,  g_wklo);
    cudaGetSymbolAddress((void**)&p_wvhi,  g_wvhi);
    cudaGetSymbolAddress((void**)&p_wvlo,  g_wvlo);
    cudaGetSymbolAddress((void**)&p_wohi,  g_wohi);
    cudaGetSymbolAddress((void**)&p_wolo,  g_wolo);
    cudaGetSymbolAddress((void**)&p_Hhi,   g_Hhi);
    cudaGetSymbolAddress((void**)&p_Hlo,   g_Hlo);
    cudaGetSymbolAddress((void**)&p_cxhi,  g_ctxhi);
    cudaGetSymbolAddress((void**)&p_cxlo,  g_ctxlo);
    cudaGetSymbolAddress((void**)&p_Qhi,   g_Qhi);
    cudaGetSymbolAddress((void**)&p_Qlo,   g_Qlo);
    cudaGetSymbolAddress((void**)&p_Khi,   g_Khi);
    cudaGetSymbolAddress((void**)&p_Klo,   g_Klo);

    cudaFuncSetAttribute(hgemm_tn_mma,
                         cudaFuncAttributeMaxDynamicSharedMemorySize, LGS_SMEM);
    cudaFuncSetAttribute(attn_scores_mma,
                         cudaFuncAttributeMaxDynamicSharedMemorySize, LGS_SMEM);
    cudaFuncSetAttribute(attn_ctx_mma,
                         cudaFuncAttributeMaxDynamicSharedMemorySize, CTX_SMEM);

    reset_k<<<1, 32>>>();

    // ---- input splits ----
    split_bf16_k<<<(V_*H_/4 + 1023)/1024, 256>>>(emb,  p_ehi,   p_elo,   V_*H_/4);
    split_bf16_k<<<(BKV_*H_/4 + 1023)/1024, 256>>>(enc, p_echi, p_eclo, BKV_*H_/4);
    split_bf16_k<<<(G4_*H_/4 + 1023)/1024, 256>>>(W_ih, p_wihhi, p_wihlo, G4_*H_/4);
    split_bf16_k<<<(H_*H_/4 + 1023)/1024, 256>>>(Wq,   p_wqhi,  p_wqlo,  H_*H_/4);
    split_bf16_k<<<(H_*H_/4 + 1023)/1024, 256>>>(Wk,   p_wkhi,  p_wklo,  H_*H_/4);
    split_bf16_k<<<(H_*H_/4 + 1023)/1024, 256>>>(Wv,   p_wvhi,  p_wvlo,  H_*H_/4);
    split_bf16_k<<<(H_*H_/4 + 1023)/1024, 256>>>(Wo,   p_wohi,  p_wolo,  H_*H_/4);

    // ---- x-gates (gather, fp32 out for rnn) ----
    hgemm_tn_mma<<<dim3(BT_/128, G4_/128), 256, LGS_SMEM>>>(
        G4_, p_ehi, p_elo, tok, p_wihhi, p_wihlo, b_ih, b_hh,
        p_xg, nullptr, nullptr);
    // ---- K projection -> bf16 hi/lo directly ----
    hgemm_tn_mma<<<dim3(BKV_/128, H_/128), 256, LGS_SMEM>>>(
        H_, p_echi, p_eclo, nullptr, p_wkhi, p_wklo, bk, nullptr,
        nullptr, p_Khi, p_Klo);
    // ---- V projection (fp32 out for the transpose) ----
    hgemm_tn_mma<<<dim3(BKV_/128, H_/128), 256, LGS_SMEM>>>(
        H_, p_echi, p_eclo, nullptr, p_wvhi, p_wvlo, bv, nullptr,
        p_V, nullptr, nullptr);
    vt_split_k<<<dim3(H_/32, SKV_/32, B_), 256>>>();

    // ---- serial LSTM recurrence ----
    rnn_kernel<<<128, 256>>>(W_hh, h0, c0);

    // ---- Q projection -> bf16 hi/lo directly ----
    split_bf16_k<<<(BT_*H_/4 + 1023)/1024, 256>>>(p_H, p_Hhi, p_Hlo, BT_*H_/4);
    hgemm_tn_mma<<<dim3(BT_/128, H_/128), 256, LGS_SMEM>>>(
        H_, p_Hhi, p_Hlo, nullptr, p_wqhi, p_wqlo, bq, nullptr,
        nullptr, p_Qhi, p_Qlo);

    // ---- attention ----
    attn_scores_mma<<<dim3(2, 8, 64), 256, LGS_SMEM>>>(mask);
    softmax_k<<<B_*NH_*S_, 128>>>();
    attn_ctx_mma<<<dim3(4, 64), 256, CTX_SMEM>>>();

    // ---- output projection -> bf16 hi/lo directly ----
    hgemm_tn_mma<<<dim3(BT_/128, H_/128), 256, LGS_SMEM>>>(
        H_, p_cxhi, p_cxlo, nullptr, p_wohi, p_wolo, bo, nullptr,
        nullptr, p_ohi, p_olo);

    // ---- tied logits ----
    hgemm_tn_mma<<<dim3(BT_/128, V_/128), 256, LGS_SMEM>>>(
        V_, p_ohi, p_olo, nullptr, p_ehi, p_elo, nullptr, nullptr,
        out, nullptr, nullptr);
}